// round 6
// baseline (speedup 1.0000x reference)
#include <cuda_runtime.h>
#include <cstdint>
#include <cstddef>

// dims fixed by dataset
#define DIM_N 1000
#define DIM_P 100000
#define DIM_B 256
#define GSPLIT 8
#define YSPLIT 20
#define NS_ITERS 5

// -------- device scratch (no allocations allowed) --------
__device__ float g_G    [DIM_N * DIM_N];
__device__ float g_Gpart[GSPLIT * DIM_N * DIM_N];
__device__ float g_Bns  [DIM_N * DIM_N];
__device__ float g_B2ns [DIM_N * DIM_N];
__device__ float g_Tns  [DIM_N * DIM_N];
__device__ float g_Y    [DIM_B * DIM_N];
__device__ float g_Ypart[YSPLIT * DIM_B * DIM_N];
__device__ float g_X    [DIM_B * DIM_N];
__device__ float g_scale[DIM_B];
__device__ float g_cvals[2];   // [0]=c (~1.05*lambda_max), [1]=1/c
__device__ float g_pv[DIM_N];
__device__ float g_pw[DIM_N];

// packed fp32x2 helpers (Blackwell FFMA2 via PTX only)
#define FMA_F32X2(d, a, b) \
    asm("fma.rn.f32x2 %0, %1, %2, %0;" : "+l"(d) : "l"(a), "l"(b))
#define PACKDUP_F32X2(d, s) \
    asm("mov.b64 %0, {%1, %1};" : "=l"(d) : "r"(__float_as_uint(s)))

__device__ __forceinline__ float lo32(unsigned long long v) {
    return __uint_as_float((unsigned)(v & 0xffffffffull));
}
__device__ __forceinline__ float hi32(unsigned long long v) {
    return __uint_as_float((unsigned)(v >> 32));
}

// ---------------------------------------------------------------------------
// SIMT fp32 GEMM, FFMA2 inner loop: 128x128 tile, BK=8, 256 threads,
// 8x8 per thread (stored as 8x4 f32x2 pairs), double-buffered smem.
//   BNT=true : B stored [N,K] k-fast -> C = A*B^T
//   BNT=false: B stored [K,N] n-fast -> C = A*B
//   SYM=true : triangular blockIdx.x decode + mirrored epilogue write (Gram)
// EPI 0: C = acc                       (split-K partial slot via blockIdx.z)
// EPI 2: C = scalePtr[row]*acc + clamp(Dptr - acc, +-1e-3)
// ---------------------------------------------------------------------------
#define BM 128
#define BN 128
#define BKK 8
#define TM 8
#define TN 8

template<bool BNT, int EPI, bool SYM>
__global__ void __launch_bounds__(256, 1)
gemm_k(const float* __restrict__ Ag, const float* __restrict__ Bg,
       float* __restrict__ Cg,
       int M, int N, int K, int lda, int ldb, int ldc,
       int kChunk,
       const float* __restrict__ scalePtr,
       const float* __restrict__ Dptr)
{
    __shared__ float As[2][BKK][BM + 4];
    __shared__ float Bs[2][BKK][BN + 4];

    const int tid = threadIdx.x;

    int bx = blockIdx.x, by = blockIdx.y;
    if (SYM) {
        // decode linear t -> (bx, by) with by >= bx (lower triangle of tile grid)
        int t = blockIdx.x;
        int r = (int)((sqrtf(8.f * (float)t + 1.f) - 1.f) * 0.5f);
        while ((r + 1) * (r + 2) / 2 <= t) ++r;
        while (r * (r + 1) / 2 > t) --r;
        by = r;
        bx = t - r * (r + 1) / 2;
    }
    const int row0 = by * BM;
    const int col0 = bx * BN;

    const int kBegin = blockIdx.z * kChunk;
    const int kEnd   = min(K, kBegin + kChunk);
    const int nTiles = (kEnd - kBegin) >> 3;

    // A loader: [M,K] row-major, k-fast
    const int ar = tid >> 1;
    const int ak = (tid & 1) << 2;
    const bool aOk = (row0 + ar) < M;
    const float* aPtr = Ag + (size_t)(row0 + ar) * lda + kBegin + ak;

    // B loader
    int b_r = 0, b_k = 0, b_n = 0;
    const float* bPtr;
    bool bOk = true;
    if (BNT) {
        b_r = tid >> 1; b_k = (tid & 1) << 2;
        bOk = (col0 + b_r) < N;
        bPtr = Bg + (size_t)(col0 + b_r) * ldb + kBegin + b_k;
    } else {
        b_k = tid >> 5;
        b_n = (tid & 31) << 2;
        bPtr = Bg + (size_t)(kBegin + b_k) * ldb + col0 + b_n;
    }

    auto ldgA = [&](int t) -> float4 {
        if (aOk) return *reinterpret_cast<const float4*>(aPtr + (size_t)t * BKK);
        return make_float4(0.f, 0.f, 0.f, 0.f);
    };
    auto ldgB = [&](int t) -> float4 {
        if (BNT) {
            if (bOk) return *reinterpret_cast<const float4*>(bPtr + (size_t)t * BKK);
            return make_float4(0.f, 0.f, 0.f, 0.f);
        } else {
            const float* p = bPtr + (size_t)t * BKK * ldb;
            int c = col0 + b_n;
            if (c + 3 < N) return *reinterpret_cast<const float4*>(p);
            float4 v = make_float4(0.f, 0.f, 0.f, 0.f);
            if (c     < N) v.x = p[0];
            if (c + 1 < N) v.y = p[1];
            if (c + 2 < N) v.z = p[2];
            if (c + 3 < N) v.w = p[3];
            return v;
        }
    };
    auto stsA = [&](int buf, float4 v) {
        As[buf][ak + 0][ar] = v.x; As[buf][ak + 1][ar] = v.y;
        As[buf][ak + 2][ar] = v.z; As[buf][ak + 3][ar] = v.w;
    };
    auto stsB = [&](int buf, float4 v) {
        if (BNT) {
            Bs[buf][b_k + 0][b_r] = v.x; Bs[buf][b_k + 1][b_r] = v.y;
            Bs[buf][b_k + 2][b_r] = v.z; Bs[buf][b_k + 3][b_r] = v.w;
        } else {
            *reinterpret_cast<float4*>(&Bs[buf][b_k][b_n]) = v;
        }
    };

    // accumulators as f32x2 pairs over adjacent output columns
    unsigned long long acc2[TM][TN / 2];
#pragma unroll
    for (int i = 0; i < TM; ++i)
#pragma unroll
        for (int jp = 0; jp < TN / 2; ++jp) acc2[i][jp] = 0ull;

    const int tx = tid & 15, ty = tid >> 4;
    const int crow = ty * TM, ccol = tx * TN;

    if (nTiles > 0) {
        stsA(0, ldgA(0)); stsB(0, ldgB(0));
        __syncthreads();
        int buf = 0;
        for (int t = 0; t < nTiles; ++t) {
            float4 aNext, bNext;
            const bool more = (t + 1 < nTiles);
            if (more) { aNext = ldgA(t + 1); bNext = ldgB(t + 1); }
#pragma unroll
            for (int kk = 0; kk < BKK; ++kk) {
                float4 a0 = *reinterpret_cast<const float4*>(&As[buf][kk][crow]);
                float4 a1 = *reinterpret_cast<const float4*>(&As[buf][kk][crow + 4]);
                ulonglong2 bq0 = *reinterpret_cast<const ulonglong2*>(&Bs[buf][kk][ccol]);
                ulonglong2 bq1 = *reinterpret_cast<const ulonglong2*>(&Bs[buf][kk][ccol + 4]);
                unsigned long long bp[4] = {bq0.x, bq0.y, bq1.x, bq1.y};
                float a[TM] = {a0.x, a0.y, a0.z, a0.w, a1.x, a1.y, a1.z, a1.w};
#pragma unroll
                for (int i = 0; i < TM; ++i) {
                    unsigned long long ad;
                    PACKDUP_F32X2(ad, a[i]);
#pragma unroll
                    for (int jp = 0; jp < TN / 2; ++jp)
                        FMA_F32X2(acc2[i][jp], ad, bp[jp]);
                }
            }
            if (more) { stsA(buf ^ 1, aNext); stsB(buf ^ 1, bNext); }
            __syncthreads();
            buf ^= 1;
        }
    }

    float* Cw = Cg + (size_t)blockIdx.z * (size_t)M * (size_t)ldc;

#pragma unroll
    for (int i = 0; i < TM; ++i) {
        const int r = row0 + crow + i;
        if (r < M) {
            float rowscale = 0.f;
            if (EPI == 2) rowscale = scalePtr[r];
#pragma unroll
            for (int j = 0; j < TN; ++j) {
                const int cc = col0 + ccol + j;
                if (cc < N) {
                    const unsigned long long pv = acc2[i][j >> 1];
                    const float v = (j & 1) ? hi32(pv) : lo32(pv);
                    const size_t idx = (size_t)r * ldc + cc;
                    if (EPI == 0) {
                        Cw[idx] = v;
                        if (SYM) Cw[(size_t)cc * ldc + r] = v;  // mirror (square)
                    } else {
                        float rsd = Dptr[idx] - v;
                        rsd = fminf(fmaxf(rsd, -1e-3f), 1e-3f);
                        Cw[idx] = fmaf(rowscale, v, rsd);
                    }
                }
            }
        }
    }
}

// -------- helpers --------
__global__ void reduce_parts(const float* __restrict__ part, float* __restrict__ out,
                             int nElem, int z, const float* __restrict__ sf) {
    int i = blockIdx.x * blockDim.x + threadIdx.x;
    if (i < nElem) {
        float s = 0.f;
        for (int k = 0; k < z; ++k) s += part[(size_t)k * nElem + i];
        if (sf) s *= sf[0];
        out[i] = s;
    }
}

// out = 2*Bin - sum(parts)   (Newton-Schulz combine)
__global__ void reduce_ns(const float* __restrict__ part, const float* __restrict__ Bin,
                          float* __restrict__ out, int nElem, int z) {
    int i = blockIdx.x * blockDim.x + threadIdx.x;
    if (i < nElem) {
        float s = 0.f;
        for (int k = 0; k < z; ++k) s += part[(size_t)k * nElem + i];
        out[i] = 2.f * Bin[i] - s;
    }
}

__global__ void scaleG_kernel(float* G, const float* cvals, int n) {
    int i = blockIdx.x * blockDim.x + threadIdx.x;
    if (i < n) G[i] *= cvals[1];
}

__global__ void init_identity(float* Bm, int n) {
    int i = blockIdx.x * blockDim.x + threadIdx.x;
    if (i < n * n) Bm[i] = ((i / n) == (i % n)) ? 1.0f : 0.0f;
}

// power iteration: lambda_max estimate of G (1000x1000)
__global__ void pi_init(float* v, int n) {
    int i = blockIdx.x * blockDim.x + threadIdx.x;
    if (i < n) v[i] = 1.0f;
}
__global__ void pi_matvec(const float* __restrict__ G, const float* __restrict__ v,
                          float* __restrict__ w, int n) {
    __shared__ float red[128];
    int r = blockIdx.x;
    float s = 0.f;
    for (int j = threadIdx.x; j < n; j += 128) s += G[(size_t)r * n + j] * v[j];
    red[threadIdx.x] = s;
    __syncthreads();
    for (int off = 64; off > 0; off >>= 1) {
        if (threadIdx.x < off) red[threadIdx.x] += red[threadIdx.x + off];
        __syncthreads();
    }
    if (threadIdx.x == 0) w[r] = red[0];
}
__global__ void pi_normalize(const float* __restrict__ w, float* __restrict__ v,
                             int n, float* cvals, int last) {
    __shared__ float red[256];
    float s = 0.f;
    for (int j = threadIdx.x; j < n; j += 256) s += w[j] * w[j];
    red[threadIdx.x] = s;
    __syncthreads();
    for (int off = 128; off > 0; off >>= 1) {
        if (threadIdx.x < off) red[threadIdx.x] += red[threadIdx.x + off];
        __syncthreads();
    }
    __syncthreads();
    float nrm = sqrtf(red[0]);
    float inv = (nrm > 0.f) ? 1.f / nrm : 0.f;
    for (int j = threadIdx.x; j < n; j += 256) v[j] = w[j] * inv;
    if (last && threadIdx.x == 0) {
        float c = nrm * 1.05f;   // safety headroom above the estimate
        cvals[0] = c;
        cvals[1] = 1.f / c;
    }
}

__global__ void calc_scale_kernel(const float* __restrict__ Y, const float* __restrict__ X,
                                  float* __restrict__ scale, int Kdim) {
    __shared__ float red[256];
    int b = blockIdx.x;
    float s = 0.f;
    for (int j = threadIdx.x; j < Kdim; j += 256)
        s += Y[(size_t)b * Kdim + j] * X[(size_t)b * Kdim + j];
    red[threadIdx.x] = s;
    __syncthreads();
    for (int off = 128; off > 0; off >>= 1) {
        if (threadIdx.x < off) red[threadIdx.x] += red[threadIdx.x + off];
        __syncthreads();
    }
    if (threadIdx.x == 0) {
        float nrm = sqrtf(fmaxf(red[0], 0.f));
        scale[b] = (nrm > 0.f) ? fminf(1.0f / nrm, 1.0f) : 1.0f;
    }
}

// ---------------------------------------------------------------------------
extern "C" void kernel_launch(void* const* d_in, const int* in_sizes, int n_in,
                              void* d_out, int out_size)
{
    const float* A    = (const float*)d_in[0];   // [1000, 100000]
    const float* priv = (const float*)d_in[1];   // [256, 100000]
    // d_in[2]=L_init, d_in[3]=power_iter: unused (output is basis-invariant)
    float* out = (float*)d_out;

    const int Nn = DIM_N, P = DIM_P, Bb = DIM_B;

    float *G, *Gpart, *Bns, *B2ns, *T, *Yb, *Ypart, *X, *scale, *cvals, *pv, *pw;
    cudaGetSymbolAddress((void**)&G,     g_G);
    cudaGetSymbolAddress((void**)&Gpart, g_Gpart);
    cudaGetSymbolAddress((void**)&Bns,   g_Bns);
    cudaGetSymbolAddress((void**)&B2ns,  g_B2ns);
    cudaGetSymbolAddress((void**)&T,     g_Tns);
    cudaGetSymbolAddress((void**)&Yb,    g_Y);
    cudaGetSymbolAddress((void**)&Ypart, g_Ypart);
    cudaGetSymbolAddress((void**)&X,     g_X);
    cudaGetSymbolAddress((void**)&scale, g_scale);
    cudaGetSymbolAddress((void**)&cvals, g_cvals);
    cudaGetSymbolAddress((void**)&pv,    g_pv);
    cudaGetSymbolAddress((void**)&pw,    g_pw);

    const int nG = Nn * Nn;

    // 1) G = A A^T, symmetric: 36 lower-triangle tiles, split-K=8
    {
        dim3 grid(36, 1, GSPLIT);
        gemm_k<true, 0, true><<<grid, 256>>>(A, A, Gpart, Nn, Nn, P, P, P, Nn,
                                             12504, nullptr, nullptr);
        reduce_parts<<<(nG + 255) / 256, 256>>>(Gpart, G, nG, GSPLIT, nullptr);
    }

    // 2) c ~= 1.05 * lambda_max(G) via 8 power-iteration steps; M = G/c in place
    pi_init<<<(Nn + 255) / 256, 256>>>(pv, Nn);
    for (int it = 0; it < 8; ++it) {
        pi_matvec<<<Nn, 128>>>(G, pv, pw, Nn);
        pi_normalize<<<1, 256>>>(pw, pv, Nn, cvals, (it == 7) ? 1 : 0);
    }
    scaleG_kernel<<<(nG + 255) / 256, 256>>>(G, cvals, nG);

    // 3) B = M^{-1} via 5 Newton-Schulz iterations, split-K=2 GEMMs:
    //    T = M*Bc ; Bo = 2*Bc - Bc*T
    init_identity<<<(nG + 255) / 256, 256>>>(Bns, Nn);
    {
        float* Bc = Bns;
        float* Bo = B2ns;
        dim3 grid(8, 8, 2);
        for (int it = 0; it < NS_ITERS; ++it) {
            gemm_k<false, 0, false><<<grid, 256>>>(G, Bc, Gpart, Nn, Nn, Nn,
                                                   Nn, Nn, Nn, 504, nullptr, nullptr);
            reduce_parts<<<(nG + 255) / 256, 256>>>(Gpart, T, nG, 2, nullptr);
            gemm_k<false, 0, false><<<grid, 256>>>(Bc, T, Gpart, Nn, Nn, Nn,
                                                   Nn, Nn, Nn, 504, nullptr, nullptr);
            reduce_ns<<<(nG + 255) / 256, 256>>>(Gpart, Bc, Bo, nG, 2);
            float* tmp = Bc; Bc = Bo; Bo = tmp;
        }
        Bns = Bc;  // final inverse of M
    }

    // 4) Y = priv A^T  (split-K=20, chunks of 5000)
    {
        dim3 grid(8, 2, YSPLIT);
        gemm_k<true, 0, false><<<grid, 256>>>(priv, A, Ypart, Bb, Nn, P, P, P, Nn,
                                              5000, nullptr, nullptr);
        reduce_parts<<<(Bb * Nn + 255) / 256, 256>>>(Ypart, Yb, Bb * Nn, YSPLIT, nullptr);
    }

    // 5) X = Y * B * (1/c)  ( = Y G^{-1} ), split-K=8 (chunk 128)
    {
        dim3 grid(8, 2, 8);
        gemm_k<false, 0, false><<<grid, 256>>>(Yb, Bns, Ypart, Bb, Nn, Nn,
                                               Nn, Nn, Nn, 128, nullptr, nullptr);
        reduce_parts<<<(Bb * Nn + 255) / 256, 256>>>(Ypart, X, Bb * Nn, 8, cvals + 1);
    }

    // 6) scale_b = min(1/||emb_b||, 1), ||emb_b||^2 = <Y_b, X_b>
    calc_scale_kernel<<<Bb, 256>>>(Yb, X, scale, Nn);

    // 7) out = scale[r] * (X A) + clamp(priv - X A, +-1e-3)
    {
        dim3 grid((P + BN - 1) / BN, (Bb + BM - 1) / BM, 1);  // (782, 2)
        gemm_k<false, 2, false><<<grid, 256>>>(X, A, out, Bb, P, Nn, Nn, P, P,
                                               Nn, scale, priv);
    }
    (void)in_sizes; (void)n_in; (void)out_size;
}

// round 9
// speedup vs baseline: 2.0479x; 2.0479x over previous
#include <cuda_runtime.h>
#include <cstdint>
#include <cstddef>

// dims fixed by dataset
#define DIM_N 1000
#define DIM_P 100000
#define DIM_B 256
#define GSPLIT 8
#define YSPLIT 18
#define NS_ITERS 5

// -------- device scratch (no allocations allowed) --------
__device__ float g_G    [DIM_N * DIM_N];
__device__ float g_Gpart[GSPLIT * DIM_N * DIM_N];
__device__ float g_Bns  [DIM_N * DIM_N];
__device__ float g_B2ns [DIM_N * DIM_N];
__device__ float g_Tns  [DIM_N * DIM_N];
__device__ float g_Y    [DIM_B * DIM_N];
__device__ float g_Ypart[YSPLIT * DIM_B * DIM_N];
__device__ float g_X    [DIM_B * DIM_N];
__device__ float g_scale[DIM_B];
__device__ float g_cvals[2];   // [0]=c (~1.05*lambda_max), [1]=1/c
__device__ float g_pv[DIM_N];
__device__ float g_pw[DIM_N];

// ---------------------------------------------------------------------------
// SIMT fp32 GEMM: 128x128 tile, BK=8, 256 threads, 8x8 per thread,
// double-buffered smem, 2 CTAs/SM.
//   BNT=true : B stored [N,K] k-fast -> C = A*B^T
//   BNT=false: B stored [K,N] n-fast -> C = A*B
//   SYM=true : triangular blockIdx.x decode + mirrored epilogue (Gram, square C)
// EPI 0: C = acc                    (split-K partial slot via blockIdx.z)
// EPI 2: C = scalePtr[row]*acc + clamp(Dptr - acc, +-1e-3)
// ---------------------------------------------------------------------------
#define BM 128
#define BN 128
#define BKK 8
#define TM 8
#define TN 8

template<bool BNT, int EPI, bool SYM>
__global__ void __launch_bounds__(256, 2)
gemm_k(const float* __restrict__ Ag, const float* __restrict__ Bg,
       float* __restrict__ Cg,
       int M, int N, int K, int lda, int ldb, int ldc,
       int kChunk,
       const float* __restrict__ scalePtr,
       const float* __restrict__ Dptr)
{
    __shared__ float As[2][BKK][BM + 4];
    __shared__ float Bs[2][BKK][BN + 4];

    const int tid = threadIdx.x;

    int bx = blockIdx.x, by = blockIdx.y;
    if (SYM) {
        // decode linear t -> (bx, by), by >= bx (lower triangle of tile grid)
        int t = blockIdx.x;
        int r = (int)((sqrtf(8.f * (float)t + 1.f) - 1.f) * 0.5f);
        while ((r + 1) * (r + 2) / 2 <= t) ++r;
        while (r * (r + 1) / 2 > t) --r;
        by = r;
        bx = t - r * (r + 1) / 2;
    }
    const int row0 = by * BM;
    const int col0 = bx * BN;

    const int kBegin = blockIdx.z * kChunk;
    const int kEnd   = min(K, kBegin + kChunk);
    const int nTiles = (kEnd - kBegin) >> 3;

    // A loader: [M,K] row-major, k-fast
    const int ar = tid >> 1;
    const int ak = (tid & 1) << 2;
    const bool aOk = (row0 + ar) < M;
    const float* aPtr = Ag + (size_t)(row0 + ar) * lda + kBegin + ak;

    // B loader
    int b_r = 0, b_k = 0, b_n = 0;
    const float* bPtr;
    bool bOk = true;
    if (BNT) {
        b_r = tid >> 1; b_k = (tid & 1) << 2;
        bOk = (col0 + b_r) < N;
        bPtr = Bg + (size_t)(col0 + b_r) * ldb + kBegin + b_k;
    } else {
        b_k = tid >> 5;
        b_n = (tid & 31) << 2;
        bPtr = Bg + (size_t)(kBegin + b_k) * ldb + col0 + b_n;
    }

    auto ldgA = [&](int t) -> float4 {
        if (aOk) return *reinterpret_cast<const float4*>(aPtr + (size_t)t * BKK);
        return make_float4(0.f, 0.f, 0.f, 0.f);
    };
    auto ldgB = [&](int t) -> float4 {
        if (BNT) {
            if (bOk) return *reinterpret_cast<const float4*>(bPtr + (size_t)t * BKK);
            return make_float4(0.f, 0.f, 0.f, 0.f);
        } else {
            const float* p = bPtr + (size_t)t * BKK * ldb;
            int c = col0 + b_n;
            if (c + 3 < N) return *reinterpret_cast<const float4*>(p);
            float4 v = make_float4(0.f, 0.f, 0.f, 0.f);
            if (c     < N) v.x = p[0];
            if (c + 1 < N) v.y = p[1];
            if (c + 2 < N) v.z = p[2];
            if (c + 3 < N) v.w = p[3];
            return v;
        }
    };
    auto stsA = [&](int buf, float4 v) {
        As[buf][ak + 0][ar] = v.x; As[buf][ak + 1][ar] = v.y;
        As[buf][ak + 2][ar] = v.z; As[buf][ak + 3][ar] = v.w;
    };
    auto stsB = [&](int buf, float4 v) {
        if (BNT) {
            Bs[buf][b_k + 0][b_r] = v.x; Bs[buf][b_k + 1][b_r] = v.y;
            Bs[buf][b_k + 2][b_r] = v.z; Bs[buf][b_k + 3][b_r] = v.w;
        } else {
            *reinterpret_cast<float4*>(&Bs[buf][b_k][b_n]) = v;
        }
    };

    float acc[TM][TN];
#pragma unroll
    for (int i = 0; i < TM; ++i)
#pragma unroll
        for (int j = 0; j < TN; ++j) acc[i][j] = 0.f;

    const int tx = tid & 15, ty = tid >> 4;
    const int crow = ty * TM, ccol = tx * TN;

    if (nTiles > 0) {
        stsA(0, ldgA(0)); stsB(0, ldgB(0));
        __syncthreads();
        int buf = 0;
        for (int t = 0; t < nTiles; ++t) {
            float4 aNext, bNext;
            const bool more = (t + 1 < nTiles);
            if (more) { aNext = ldgA(t + 1); bNext = ldgB(t + 1); }
#pragma unroll
            for (int kk = 0; kk < BKK; ++kk) {
                float4 a0 = *reinterpret_cast<const float4*>(&As[buf][kk][crow]);
                float4 a1 = *reinterpret_cast<const float4*>(&As[buf][kk][crow + 4]);
                float4 b0 = *reinterpret_cast<const float4*>(&Bs[buf][kk][ccol]);
                float4 b1 = *reinterpret_cast<const float4*>(&Bs[buf][kk][ccol + 4]);
                float a[TM] = {a0.x, a0.y, a0.z, a0.w, a1.x, a1.y, a1.z, a1.w};
                float b[TN] = {b0.x, b0.y, b0.z, b0.w, b1.x, b1.y, b1.z, b1.w};
#pragma unroll
                for (int i = 0; i < TM; ++i)
#pragma unroll
                    for (int j = 0; j < TN; ++j)
                        acc[i][j] = fmaf(a[i], b[j], acc[i][j]);
            }
            if (more) { stsA(buf ^ 1, aNext); stsB(buf ^ 1, bNext); }
            __syncthreads();
            buf ^= 1;
        }
    }

    float* Cw = Cg + (size_t)blockIdx.z * (size_t)M * (size_t)ldc;

#pragma unroll
    for (int i = 0; i < TM; ++i) {
        const int r = row0 + crow + i;
        if (r < M) {
            float rowscale = 0.f;
            if (EPI == 2) rowscale = scalePtr[r];
#pragma unroll
            for (int j = 0; j < TN; ++j) {
                const int cc = col0 + ccol + j;
                if (cc < N) {
                    const float v = acc[i][j];
                    const size_t idx = (size_t)r * ldc + cc;
                    if (EPI == 0) {
                        Cw[idx] = v;
                        if (SYM) Cw[(size_t)cc * ldc + r] = v;  // mirror
                    } else {
                        float rsd = Dptr[idx] - v;
                        rsd = fminf(fmaxf(rsd, -1e-3f), 1e-3f);
                        Cw[idx] = fmaf(rowscale, v, rsd);
                    }
                }
            }
        }
    }
}

// -------- helpers --------
__global__ void reduce_parts(const float* __restrict__ part, float* __restrict__ out,
                             int nElem, int z, const float* __restrict__ sf) {
    int i = blockIdx.x * blockDim.x + threadIdx.x;
    if (i < nElem) {
        float s = 0.f;
        for (int k = 0; k < z; ++k) s += part[(size_t)k * nElem + i];
        if (sf) s *= sf[0];
        out[i] = s;
    }
}

// out = 2*Bin - sum(parts)   (Newton-Schulz combine)
__global__ void reduce_ns(const float* __restrict__ part, const float* __restrict__ Bin,
                          float* __restrict__ out, int nElem, int z) {
    int i = blockIdx.x * blockDim.x + threadIdx.x;
    if (i < nElem) {
        float s = 0.f;
        for (int k = 0; k < z; ++k) s += part[(size_t)k * nElem + i];
        out[i] = 2.f * Bin[i] - s;
    }
}

__global__ void scaleG_kernel(float* G, const float* cvals, int n) {
    int i = blockIdx.x * blockDim.x + threadIdx.x;
    if (i < n) G[i] *= cvals[1];
}

__global__ void init_identity(float* Bm, int n) {
    int i = blockIdx.x * blockDim.x + threadIdx.x;
    if (i < n * n) Bm[i] = ((i / n) == (i % n)) ? 1.0f : 0.0f;
}

// power iteration: lambda_max estimate of G (1000x1000)
__global__ void pi_init(float* v, int n) {
    int i = blockIdx.x * blockDim.x + threadIdx.x;
    if (i < n) v[i] = 1.0f;
}
__global__ void pi_matvec(const float* __restrict__ G, const float* __restrict__ v,
                          float* __restrict__ w, int n) {
    __shared__ float red[128];
    int r = blockIdx.x;
    float s = 0.f;
    for (int j = threadIdx.x; j < n; j += 128) s += G[(size_t)r * n + j] * v[j];
    red[threadIdx.x] = s;
    __syncthreads();
    for (int off = 64; off > 0; off >>= 1) {
        if (threadIdx.x < off) red[threadIdx.x] += red[threadIdx.x + off];
        __syncthreads();
    }
    if (threadIdx.x == 0) w[r] = red[0];
}
__global__ void pi_normalize(const float* __restrict__ w, float* __restrict__ v,
                             int n, float* cvals, int last) {
    __shared__ float red[256];
    float s = 0.f;
    for (int j = threadIdx.x; j < n; j += 256) s += w[j] * w[j];
    red[threadIdx.x] = s;
    __syncthreads();
    for (int off = 128; off > 0; off >>= 1) {
        if (threadIdx.x < off) red[threadIdx.x] += red[threadIdx.x + off];
        __syncthreads();
    }
    __syncthreads();
    float nrm = sqrtf(red[0]);
    float inv = (nrm > 0.f) ? 1.f / nrm : 0.f;
    for (int j = threadIdx.x; j < n; j += 256) v[j] = w[j] * inv;
    if (last && threadIdx.x == 0) {
        float c = nrm * 1.05f;   // headroom above the estimate
        cvals[0] = c;
        cvals[1] = 1.f / c;
    }
}

__global__ void calc_scale_kernel(const float* __restrict__ Y, const float* __restrict__ X,
                                  float* __restrict__ scale, int Kdim) {
    __shared__ float red[256];
    int b = blockIdx.x;
    float s = 0.f;
    for (int j = threadIdx.x; j < Kdim; j += 256)
        s += Y[(size_t)b * Kdim + j] * X[(size_t)b * Kdim + j];
    red[threadIdx.x] = s;
    __syncthreads();
    for (int off = 128; off > 0; off >>= 1) {
        if (threadIdx.x < off) red[threadIdx.x] += red[threadIdx.x + off];
        __syncthreads();
    }
    if (threadIdx.x == 0) {
        float nrm = sqrtf(fmaxf(red[0], 0.f));
        scale[b] = (nrm > 0.f) ? fminf(1.0f / nrm, 1.0f) : 1.0f;
    }
}

// ---------------------------------------------------------------------------
extern "C" void kernel_launch(void* const* d_in, const int* in_sizes, int n_in,
                              void* d_out, int out_size)
{
    const float* A    = (const float*)d_in[0];   // [1000, 100000]
    const float* priv = (const float*)d_in[1];   // [256, 100000]
    // d_in[2]=L_init, d_in[3]=power_iter: unused (output is basis-invariant)
    float* out = (float*)d_out;

    const int Nn = DIM_N, P = DIM_P, Bb = DIM_B;

    float *G, *Gpart, *Bns, *B2ns, *T, *Yb, *Ypart, *X, *scale, *cvals, *pv, *pw;
    cudaGetSymbolAddress((void**)&G,     g_G);
    cudaGetSymbolAddress((void**)&Gpart, g_Gpart);
    cudaGetSymbolAddress((void**)&Bns,   g_Bns);
    cudaGetSymbolAddress((void**)&B2ns,  g_B2ns);
    cudaGetSymbolAddress((void**)&T,     g_Tns);
    cudaGetSymbolAddress((void**)&Yb,    g_Y);
    cudaGetSymbolAddress((void**)&Ypart, g_Ypart);
    cudaGetSymbolAddress((void**)&X,     g_X);
    cudaGetSymbolAddress((void**)&scale, g_scale);
    cudaGetSymbolAddress((void**)&cvals, g_cvals);
    cudaGetSymbolAddress((void**)&pv,    g_pv);
    cudaGetSymbolAddress((void**)&pw,    g_pw);

    const int nG = Nn * Nn;

    // 1) G = A A^T, symmetric: 36 lower-triangle tiles, split-K=8
    //    grid = 36*8 = 288 CTAs ~ one wave at 2 CTAs/SM on 148 SMs.
    {
        dim3 grid(36, 1, GSPLIT);
        gemm_k<true, 0, true><<<grid, 256>>>(A, A, Gpart, Nn, Nn, P, P, P, Nn,
                                             12504, nullptr, nullptr);
        reduce_parts<<<(nG + 255) / 256, 256>>>(Gpart, G, nG, GSPLIT, nullptr);
    }

    // 2) c ~= 1.05 * lambda_max(G) via 8 power-iteration steps; M = G/c in place
    pi_init<<<(Nn + 255) / 256, 256>>>(pv, Nn);
    for (int it = 0; it < 8; ++it) {
        pi_matvec<<<Nn, 128>>>(G, pv, pw, Nn);
        pi_normalize<<<1, 256>>>(pw, pv, Nn, cvals, (it == 7) ? 1 : 0);
    }
    scaleG_kernel<<<(nG + 255) / 256, 256>>>(G, cvals, nG);

    // 3) B = M^{-1} via 5 Newton-Schulz iterations (split-K=2):
    //    T = M*Bc ; Bo = 2*Bc - Bc*T
    init_identity<<<(nG + 255) / 256, 256>>>(Bns, Nn);
    {
        float* Bc = Bns;
        float* Bo = B2ns;
        dim3 grid(8, 8, 2);
        for (int it = 0; it < NS_ITERS; ++it) {
            gemm_k<false, 0, false><<<grid, 256>>>(G, Bc, Gpart, Nn, Nn, Nn,
                                                   Nn, Nn, Nn, 504, nullptr, nullptr);
            reduce_parts<<<(nG + 255) / 256, 256>>>(Gpart, T, nG, 2, nullptr);
            gemm_k<false, 0, false><<<grid, 256>>>(Bc, T, Gpart, Nn, Nn, Nn,
                                                   Nn, Nn, Nn, 504, nullptr, nullptr);
            reduce_ns<<<(nG + 255) / 256, 256>>>(Gpart, Bc, Bo, nG, 2);
            float* tmp = Bc; Bc = Bo; Bo = tmp;
        }
        Bns = Bc;  // final inverse of M
    }

    // 4) Y = priv A^T  (split-K=18: 16*18 = 288 CTAs = one wave; chunks of 5560)
    {
        dim3 grid(8, 2, YSPLIT);
        gemm_k<true, 0, false><<<grid, 256>>>(priv, A, Ypart, Bb, Nn, P, P, P, Nn,
                                              5560, nullptr, nullptr);
        reduce_parts<<<(Bb * Nn + 255) / 256, 256>>>(Ypart, Yb, Bb * Nn, YSPLIT, nullptr);
    }

    // 5) X = Y * B * (1/c)  ( = Y G^{-1} ), split-K=8 (chunk 128)
    {
        dim3 grid(8, 2, 8);
        gemm_k<false, 0, false><<<grid, 256>>>(Yb, Bns, Ypart, Bb, Nn, Nn,
                                               Nn, Nn, Nn, 128, nullptr, nullptr);
        reduce_parts<<<(Bb * Nn + 255) / 256, 256>>>(Ypart, X, Bb * Nn, 8, cvals + 1);
    }

    // 6) scale_b = min(1/||emb_b||, 1), ||emb_b||^2 = <Y_b, X_b>
    calc_scale_kernel<<<Bb, 256>>>(Yb, X, scale, Nn);

    // 7) out = scale[r] * (X A) + clamp(priv - X A, +-1e-3)
    {
        dim3 grid((P + BN - 1) / BN, (Bb + BM - 1) / BM, 1);  // (782, 2)
        gemm_k<false, 2, false><<<grid, 256>>>(X, A, out, Bb, P, Nn, Nn, P, P,
                                               Nn, scale, priv);
    }
    (void)in_sizes; (void)n_in; (void)out_size;
}

// round 14
// speedup vs baseline: 3.3840x; 1.6524x over previous
#include <cuda_runtime.h>
#include <cuda_bf16.h>
#include <cstdint>
#include <cstddef>

// dims fixed by dataset
#define DIM_N 1000
#define DIM_P 100000
#define DIM_B 256
#define GSPLIT 4
#define YSPLIT 9
#define NS_ITERS 5

// -------- device scratch (no allocations allowed) --------
__device__ float g_G    [DIM_N * DIM_N];
__device__ float g_Gpart[GSPLIT * DIM_N * DIM_N];
__device__ float g_Bns  [DIM_N * DIM_N];
__device__ float g_B2ns [DIM_N * DIM_N];
__device__ float g_Tns  [DIM_N * DIM_N];
__device__ float g_Y    [DIM_B * DIM_N];
__device__ float g_Ypart[YSPLIT * DIM_B * DIM_N];
__device__ float g_X    [DIM_B * DIM_N];
__device__ float g_scale[DIM_B];
__device__ float g_cvals[2];   // [0]=c (~1.05*lambda_max), [1]=1/c
__device__ float g_pv[DIM_N];
__device__ float g_pw[DIM_N];

// bf16 hi/lo splits (16B aligned)
__device__ __align__(16) __nv_bfloat16 g_Ahi [DIM_N * DIM_P];
__device__ __align__(16) __nv_bfloat16 g_Alo [DIM_N * DIM_P];
__device__ __align__(16) __nv_bfloat16 g_AThi[(size_t)DIM_P * DIM_N];
__device__ __align__(16) __nv_bfloat16 g_ATlo[(size_t)DIM_P * DIM_N];
__device__ __align__(16) __nv_bfloat16 g_Phi [DIM_B * DIM_P];
__device__ __align__(16) __nv_bfloat16 g_Plo [DIM_B * DIM_P];
__device__ __align__(16) __nv_bfloat16 g_Xhi [DIM_B * DIM_N];
__device__ __align__(16) __nv_bfloat16 g_Xlo [DIM_B * DIM_N];

// =========================================================================
// warp-mma primitives (NO 'a'-suffix features: work on plain sm_103 target)
// =========================================================================
__device__ __forceinline__ uint32_t smem_u32(const void* p) {
    uint32_t a;
    asm("{ .reg .u64 t; cvta.to.shared.u64 t, %1; cvt.u32.u64 %0, t; }"
        : "=r"(a) : "l"(p));
    return a;
}
__device__ __forceinline__ void cp_async16(uint32_t dst, const void* src, bool pred) {
    int sz = pred ? 16 : 0;
    asm volatile("cp.async.cg.shared.global [%0], [%1], 16, %2;\n"
                 :: "r"(dst), "l"(src), "r"(sz));
}
#define CP_COMMIT() asm volatile("cp.async.commit_group;\n" ::: "memory")
#define CP_WAIT1()  asm volatile("cp.async.wait_group 1;\n" ::: "memory")
#define CP_WAIT0()  asm volatile("cp.async.wait_group 0;\n" ::: "memory")

#define LDSM_X4(r0, r1, r2, r3, addr) \
    asm volatile("ldmatrix.sync.aligned.m8n8.x4.shared.b16 {%0,%1,%2,%3}, [%4];" \
                 : "=r"(r0), "=r"(r1), "=r"(r2), "=r"(r3) : "r"(addr))

#define MMA_BF16(c, a, b) \
    asm volatile("mma.sync.aligned.m16n8k16.row.col.f32.bf16.bf16.f32 " \
                 "{%0,%1,%2,%3}, {%4,%5,%6,%7}, {%8,%9}, {%0,%1,%2,%3};" \
                 : "+f"((c)[0]), "+f"((c)[1]), "+f"((c)[2]), "+f"((c)[3]) \
                 : "r"((a)[0]), "r"((a)[1]), "r"((a)[2]), "r"((a)[3]), \
                   "r"((b)[0]), "r"((b)[1]))

// =========================================================================
// mma_gemm: C[M,N] (+)= A*B^T with bf16x3 split (AhBh + AlBh + AhBl).
// A[M,K], B[N,K] both k-major bf16 (hi/lo), common ld. fp32 accum in regs.
// 128x128 CTA tile, BK=32, 8 warps (warp_m = wid&3 -> 32 rows,
// warp_n = wid>>2 -> 64 cols). cp.async double-buffered smem.
// smem tile rows padded to 40 bf16 (80B): cp.async stores and ldmatrix
// reads are bank-conflict-free. Per stage: 4 tiles (Ah,Al,Bh,Bl) x 10240B.
//  EPI 0: C partial slot via blockIdx.z; SYM: triangular decode + mirror.
//  EPI 2: C = scalePtr[row]*acc + clamp(Dptr - acc, +-1e-3)
// =========================================================================
#define MM_SMEM (2 * 4 * 10240)   // 81920 B

template<int EPI, bool SYM>
__global__ void __launch_bounds__(256, 1)
mma_gemm(const __nv_bfloat16* __restrict__ Ahi, const __nv_bfloat16* __restrict__ Alo,
         const __nv_bfloat16* __restrict__ Bhi, const __nv_bfloat16* __restrict__ Blo,
         float* __restrict__ Cg,
         int M, int N, int K, int ld, int ldc, int kChunk,
         const float* __restrict__ scalePtr, const float* __restrict__ Dptr)
{
    extern __shared__ __align__(16) char smem[];
    const uint32_t sb = smem_u32(smem);
    const int tid = threadIdx.x, wid = tid >> 5, lane = tid & 31;
    const int warp_m = wid & 3, warp_n = wid >> 2;

    int bx = blockIdx.x, by = blockIdx.y;
    if (SYM) {
        int t = blockIdx.x;
        int r = (int)((sqrtf(8.f * (float)t + 1.f) - 1.f) * 0.5f);
        while ((r + 1) * (r + 2) / 2 <= t) ++r;
        while (r * (r + 1) / 2 > t) --r;
        by = r; bx = t - r * (r + 1) / 2;
    }
    const int row0 = by * 128;
    const int col0 = bx * 128;

    const int kBegin = blockIdx.z * kChunk;
    const int kEnd   = min(K, kBegin + kChunk);
    const int nCh    = (kEnd - kBegin + 31) >> 5;

    const int rowsA = M - row0;
    const int rowsB = N - col0;

    // ---- loader: 4 tiles x 128 rows x 4 x 16B chunks = 8 cp.async / thread
    auto issue_load = [&](int t, int buf) {
        const int kb = kBegin + (t << 5);
        const int kValid = kEnd - kb;   // multiple of 8
#pragma unroll
        for (int it = 0; it < 8; ++it) {
            int idx = it * 256 + tid;
            int tile = idx >> 9;          // 0..3
            int r    = (idx >> 2) & 127;
            int c    = idx & 3;
            const __nv_bfloat16* src;
            int rbase, rows;
            if (tile < 2) { rbase = row0; rows = rowsA; src = (tile == 0) ? Ahi : Alo; }
            else          { rbase = col0; rows = rowsB; src = (tile == 2) ? Bhi : Blo; }
            bool ok = (r < rows) && (c * 8 < kValid);
            const void* gp = ok
                ? (const void*)(src + (size_t)(rbase + r) * ld + kb + c * 8)
                : (const void*)src;
            uint32_t sp = sb + (uint32_t)(buf * 40960 + tile * 10240 + r * 80 + c * 16);
            cp_async16(sp, gp, ok);
        }
        CP_COMMIT();
    };

    // ---- ldmatrix address bases (bytes within a stage)
    // A frag (m16k16, x4): lanes 0-15 -> rows 0-15 @k, lanes 16-31 -> rows @k+8
    const uint32_t aBase = (uint32_t)(((warp_m * 32 + (lane & 15)) * 40 +
                                       ((lane >> 4) & 1) * 8) * 2);
    // B frag pair (2 n8-tiles per x4): lanes0-7 nt0@k, 8-15 nt0@k+8,
    // 16-23 nt1@k, 24-31 nt1@k+8
    const uint32_t bBase = (uint32_t)(((warp_n * 64 + ((lane >> 4) & 1) * 8 +
                                        (lane & 7)) * 40 +
                                       ((lane >> 3) & 1) * 8) * 2);

    float acc[2][8][4];
#pragma unroll
    for (int i = 0; i < 2; ++i)
#pragma unroll
        for (int j = 0; j < 8; ++j)
#pragma unroll
            for (int q = 0; q < 4; ++q) acc[i][j][q] = 0.f;

    issue_load(0, 0);

    for (int t = 0; t < nCh; ++t) {
        const int buf = t & 1;
        if (t + 1 < nCh) { issue_load(t + 1, buf ^ 1); CP_WAIT1(); }
        else             { CP_WAIT0(); }
        __syncthreads();

        const uint32_t sOff = sb + (uint32_t)(buf * 40960);
        uint32_t aH[2][4], aL[2][4], bF[4][4];
#pragma unroll
        for (int kk = 0; kk < 2; ++kk) {
            const uint32_t ko = kk * 32;   // 16 bf16 = 32 bytes
#pragma unroll
            for (int i = 0; i < 2; ++i) {
                uint32_t ad = sOff + aBase + i * 1280 + ko;
                LDSM_X4(aH[i][0], aH[i][1], aH[i][2], aH[i][3], ad);
                LDSM_X4(aL[i][0], aL[i][1], aL[i][2], aL[i][3], ad + 10240);
            }
#pragma unroll
            for (int jp = 0; jp < 4; ++jp) {
                uint32_t bd = sOff + 20480 + bBase + jp * 1280 + ko;
                LDSM_X4(bF[jp][0], bF[jp][1], bF[jp][2], bF[jp][3], bd);
            }
#pragma unroll
            for (int i = 0; i < 2; ++i)
#pragma unroll
                for (int j = 0; j < 8; ++j) {
                    MMA_BF16(acc[i][j], aH[i], (&bF[j >> 1][(j & 1) * 2]));
                    MMA_BF16(acc[i][j], aL[i], (&bF[j >> 1][(j & 1) * 2]));
                }
#pragma unroll
            for (int jp = 0; jp < 4; ++jp) {
                uint32_t bd = sOff + 30720 + bBase + jp * 1280 + ko;  // Bl tile
                LDSM_X4(bF[jp][0], bF[jp][1], bF[jp][2], bF[jp][3], bd);
            }
#pragma unroll
            for (int i = 0; i < 2; ++i)
#pragma unroll
                for (int j = 0; j < 8; ++j)
                    MMA_BF16(acc[i][j], aH[i], (&bF[j >> 1][(j & 1) * 2]));
        }
        __syncthreads();
    }

    // ---- epilogue: c-frag m16n8: {c0,c1}=(lane/4, 2*(lane%4)+{0,1}),
    //               {c2,c3}=(lane/4+8, same cols)
    const int lr = lane >> 2;
    const int lc = (lane & 3) * 2;
    float* Cw = (EPI == 0)
        ? Cg + (size_t)blockIdx.z * (size_t)M * (size_t)ldc
        : Cg;

#pragma unroll
    for (int i = 0; i < 2; ++i) {
#pragma unroll
        for (int h = 0; h < 2; ++h) {
            const int r = row0 + warp_m * 32 + i * 16 + h * 8 + lr;
            if (r < M) {
                float rowscale = 0.f;
                if (EPI == 2) rowscale = scalePtr[r];
#pragma unroll
                for (int j = 0; j < 8; ++j) {
                    const int cc = col0 + warp_n * 64 + j * 8 + lc;
#pragma unroll
                    for (int q = 0; q < 2; ++q) {
                        const int ccq = cc + q;
                        if (ccq < N) {
                            const float v = acc[i][j][h * 2 + q];
                            const size_t idx = (size_t)r * ldc + ccq;
                            if (EPI == 0) {
                                Cw[idx] = v;
                                if (SYM) Cw[(size_t)ccq * ldc + r] = v;
                            } else {
                                float rsd = Dptr[idx] - v;
                                rsd = fminf(fmaxf(rsd, -1e-3f), 1e-3f);
                                Cw[idx] = fmaf(rowscale, v, rsd);
                            }
                        }
                    }
                }
            }
        }
    }
}

// =========================================================================
// Scalar fp32 GEMM (small 1000^3 NS GEMMs and X solve) — proven R9 version
// =========================================================================
#define BM 128
#define BN 128
#define BKK 8
#define TM 8
#define TN 8

__global__ void __launch_bounds__(256, 2)
sgemm_nn(const float* __restrict__ Ag, const float* __restrict__ Bg,
         float* __restrict__ Cg,
         int M, int N, int K, int lda, int ldb, int ldc, int kChunk)
{
    __shared__ float As[2][BKK][BM + 4];
    __shared__ float Bs[2][BKK][BN + 4];

    const int tid = threadIdx.x;
    const int row0 = blockIdx.y * BM;
    const int col0 = blockIdx.x * BN;
    const int kBegin = blockIdx.z * kChunk;
    const int kEnd   = min(K, kBegin + kChunk);
    const int nTiles = (kEnd - kBegin) >> 3;

    const int ar = tid >> 1;
    const int ak = (tid & 1) << 2;
    const bool aOk = (row0 + ar) < M;
    const float* aPtr = Ag + (size_t)(row0 + ar) * lda + kBegin + ak;

    const int b_k = tid >> 5;
    const int b_n = (tid & 31) << 2;
    const float* bPtr = Bg + (size_t)(kBegin + b_k) * ldb + col0 + b_n;

    auto ldgA = [&](int t) -> float4 {
        if (aOk) return *reinterpret_cast<const float4*>(aPtr + (size_t)t * BKK);
        return make_float4(0.f, 0.f, 0.f, 0.f);
    };
    auto ldgB = [&](int t) -> float4 {
        const float* p = bPtr + (size_t)t * BKK * ldb;
        int c = col0 + b_n;
        if (c + 3 < N) return *reinterpret_cast<const float4*>(p);
        float4 v = make_float4(0.f, 0.f, 0.f, 0.f);
        if (c     < N) v.x = p[0];
        if (c + 1 < N) v.y = p[1];
        if (c + 2 < N) v.z = p[2];
        if (c + 3 < N) v.w = p[3];
        return v;
    };
    auto stsA = [&](int buf, float4 v) {
        As[buf][ak + 0][ar] = v.x; As[buf][ak + 1][ar] = v.y;
        As[buf][ak + 2][ar] = v.z; As[buf][ak + 3][ar] = v.w;
    };
    auto stsB = [&](int buf, float4 v) {
        *reinterpret_cast<float4*>(&Bs[buf][b_k][b_n]) = v;
    };

    float acc[TM][TN];
#pragma unroll
    for (int i = 0; i < TM; ++i)
#pragma unroll
        for (int j = 0; j < TN; ++j) acc[i][j] = 0.f;

    const int tx = tid & 15, ty = tid >> 4;
    const int crow = ty * TM, ccol = tx * TN;

    if (nTiles > 0) {
        stsA(0, ldgA(0)); stsB(0, ldgB(0));
        __syncthreads();
        int buf = 0;
        for (int t = 0; t < nTiles; ++t) {
            float4 aNext, bNext;
            const bool more = (t + 1 < nTiles);
            if (more) { aNext = ldgA(t + 1); bNext = ldgB(t + 1); }
#pragma unroll
            for (int kk = 0; kk < BKK; ++kk) {
                float4 a0 = *reinterpret_cast<const float4*>(&As[buf][kk][crow]);
                float4 a1 = *reinterpret_cast<const float4*>(&As[buf][kk][crow + 4]);
                float4 b0 = *reinterpret_cast<const float4*>(&Bs[buf][kk][ccol]);
                float4 b1 = *reinterpret_cast<const float4*>(&Bs[buf][kk][ccol + 4]);
                float a[TM] = {a0.x, a0.y, a0.z, a0.w, a1.x, a1.y, a1.z, a1.w};
                float b[TN] = {b0.x, b0.y, b0.z, b0.w, b1.x, b1.y, b1.z, b1.w};
#pragma unroll
                for (int i = 0; i < TM; ++i)
#pragma unroll
                    for (int j = 0; j < TN; ++j)
                        acc[i][j] = fmaf(a[i], b[j], acc[i][j]);
            }
            if (more) { stsA(buf ^ 1, aNext); stsB(buf ^ 1, bNext); }
            __syncthreads();
            buf ^= 1;
        }
    }

    float* Cw = Cg + (size_t)blockIdx.z * (size_t)M * (size_t)ldc;
#pragma unroll
    for (int i = 0; i < TM; ++i) {
        const int r = row0 + crow + i;
        if (r < M) {
#pragma unroll
            for (int j = 0; j < TN; ++j) {
                const int cc = col0 + ccol + j;
                if (cc < N) Cw[(size_t)r * ldc + cc] = acc[i][j];
            }
        }
    }
}

// -------- conversion / transpose --------
__global__ void cvt_split(const float* __restrict__ src,
                          __nv_bfloat16* __restrict__ hi,
                          __nv_bfloat16* __restrict__ lo, size_t n) {
    size_t i = (size_t)blockIdx.x * blockDim.x + threadIdx.x;
    if (i < n) {
        float x = src[i];
        __nv_bfloat16 h = __float2bfloat16(x);
        hi[i] = h;
        lo[i] = __float2bfloat16(x - __bfloat162float(h));
    }
}

__global__ void transpose_split(const float* __restrict__ A,
                                __nv_bfloat16* __restrict__ ATh,
                                __nv_bfloat16* __restrict__ ATl,
                                int K, int P) {
    __shared__ float t[32][33];
    int pb = blockIdx.x * 32, kb = blockIdx.y * 32;
    int tx = threadIdx.x, ty = threadIdx.y;
#pragma unroll
    for (int j = 0; j < 4; ++j) {
        int k = kb + ty + j * 8;
        if (k < K) t[ty + j * 8][tx] = A[(size_t)k * P + pb + tx];
    }
    __syncthreads();
#pragma unroll
    for (int j = 0; j < 4; ++j) {
        int p = pb + ty + j * 8;
        int k = kb + tx;
        if (k < K) {
            float x = t[tx][ty + j * 8];
            __nv_bfloat16 h = __float2bfloat16(x);
            size_t idx = (size_t)p * K + k;
            ATh[idx] = h;
            ATl[idx] = __float2bfloat16(x - __bfloat162float(h));
        }
    }
}

// -------- small helpers (unchanged, R9-proven) --------
__global__ void reduce_parts(const float* __restrict__ part, float* __restrict__ out,
                             int nElem, int z, const float* __restrict__ sf) {
    int i = blockIdx.x * blockDim.x + threadIdx.x;
    if (i < nElem) {
        float s = 0.f;
        for (int k = 0; k < z; ++k) s += part[(size_t)k * nElem + i];
        if (sf) s *= sf[0];
        out[i] = s;
    }
}
__global__ void reduce_ns(const float* __restrict__ part, const float* __restrict__ Bin,
                          float* __restrict__ out, int nElem, int z) {
    int i = blockIdx.x * blockDim.x + threadIdx.x;
    if (i < nElem) {
        float s = 0.f;
        for (int k = 0; k < z; ++k) s += part[(size_t)k * nElem + i];
        out[i] = 2.f * Bin[i] - s;
    }
}
__global__ void scaleG_kernel(float* G, const float* cvals, int n) {
    int i = blockIdx.x * blockDim.x + threadIdx.x;
    if (i < n) G[i] *= cvals[1];
}
__global__ void init_identity(float* Bm, int n) {
    int i = blockIdx.x * blockDim.x + threadIdx.x;
    if (i < n * n) Bm[i] = ((i / n) == (i % n)) ? 1.0f : 0.0f;
}
__global__ void pi_init(float* v, int n) {
    int i = blockIdx.x * blockDim.x + threadIdx.x;
    if (i < n) v[i] = 1.0f;
}
__global__ void pi_matvec(const float* __restrict__ G, const float* __restrict__ v,
                          float* __restrict__ w, int n) {
    __shared__ float red[128];
    int r = blockIdx.x;
    float s = 0.f;
    for (int j = threadIdx.x; j < n; j += 128) s += G[(size_t)r * n + j] * v[j];
    red[threadIdx.x] = s;
    __syncthreads();
    for (int off = 64; off > 0; off >>= 1) {
        if (threadIdx.x < off) red[threadIdx.x] += red[threadIdx.x + off];
        __syncthreads();
    }
    if (threadIdx.x == 0) w[r] = red[0];
}
__global__ void pi_normalize(const float* __restrict__ w, float* __restrict__ v,
                             int n, float* cvals, int last) {
    __shared__ float red[256];
    float s = 0.f;
    for (int j = threadIdx.x; j < n; j += 256) s += w[j] * w[j];
    red[threadIdx.x] = s;
    __syncthreads();
    for (int off = 128; off > 0; off >>= 1) {
        if (threadIdx.x < off) red[threadIdx.x] += red[threadIdx.x + off];
        __syncthreads();
    }
    __syncthreads();
    float nrm = sqrtf(red[0]);
    float inv = (nrm > 0.f) ? 1.f / nrm : 0.f;
    for (int j = threadIdx.x; j < n; j += 256) v[j] = w[j] * inv;
    if (last && threadIdx.x == 0) {
        float c = nrm * 1.05f;
        cvals[0] = c;
        cvals[1] = 1.f / c;
    }
}
__global__ void calc_scale_kernel(const float* __restrict__ Y, const float* __restrict__ X,
                                  float* __restrict__ scale, int Kdim) {
    __shared__ float red[256];
    int b = blockIdx.x;
    float s = 0.f;
    for (int j = threadIdx.x; j < Kdim; j += 256)
        s += Y[(size_t)b * Kdim + j] * X[(size_t)b * Kdim + j];
    red[threadIdx.x] = s;
    __syncthreads();
    for (int off = 128; off > 0; off >>= 1) {
        if (threadIdx.x < off) red[threadIdx.x] += red[threadIdx.x + off];
        __syncthreads();
    }
    if (threadIdx.x == 0) {
        float nrm = sqrtf(fmaxf(red[0], 0.f));
        scale[b] = (nrm > 0.f) ? fminf(1.0f / nrm, 1.0f) : 1.0f;
    }
}

// ---------------------------------------------------------------------------
extern "C" void kernel_launch(void* const* d_in, const int* in_sizes, int n_in,
                              void* d_out, int out_size)
{
    const float* A    = (const float*)d_in[0];   // [1000, 100000]
    const float* priv = (const float*)d_in[1];   // [256, 100000]
    float* out = (float*)d_out;

    const int Nn = DIM_N, P = DIM_P, Bb = DIM_B;

    float *G, *Gpart, *Bns, *B2ns, *T, *Yb, *Ypart, *X, *scale, *cvals, *pv, *pw;
    __nv_bfloat16 *Ahi, *Alo, *AThi, *ATlo, *Phi, *Plo, *Xhi, *Xlo;
    cudaGetSymbolAddress((void**)&G,     g_G);
    cudaGetSymbolAddress((void**)&Gpart, g_Gpart);
    cudaGetSymbolAddress((void**)&Bns,   g_Bns);
    cudaGetSymbolAddress((void**)&B2ns,  g_B2ns);
    cudaGetSymbolAddress((void**)&T,     g_Tns);
    cudaGetSymbolAddress((void**)&Yb,    g_Y);
    cudaGetSymbolAddress((void**)&Ypart, g_Ypart);
    cudaGetSymbolAddress((void**)&X,     g_X);
    cudaGetSymbolAddress((void**)&scale, g_scale);
    cudaGetSymbolAddress((void**)&cvals, g_cvals);
    cudaGetSymbolAddress((void**)&pv,    g_pv);
    cudaGetSymbolAddress((void**)&pw,    g_pw);
    cudaGetSymbolAddress((void**)&Ahi,   g_Ahi);
    cudaGetSymbolAddress((void**)&Alo,   g_Alo);
    cudaGetSymbolAddress((void**)&AThi,  g_AThi);
    cudaGetSymbolAddress((void**)&ATlo,  g_ATlo);
    cudaGetSymbolAddress((void**)&Phi,   g_Phi);
    cudaGetSymbolAddress((void**)&Plo,   g_Plo);
    cudaGetSymbolAddress((void**)&Xhi,   g_Xhi);
    cudaGetSymbolAddress((void**)&Xlo,   g_Xlo);

    cudaFuncSetAttribute(mma_gemm<0, true>,
                         cudaFuncAttributeMaxDynamicSharedMemorySize, MM_SMEM);
    cudaFuncSetAttribute(mma_gemm<0, false>,
                         cudaFuncAttributeMaxDynamicSharedMemorySize, MM_SMEM);
    cudaFuncSetAttribute(mma_gemm<2, false>,
                         cudaFuncAttributeMaxDynamicSharedMemorySize, MM_SMEM);

    const int nG = Nn * Nn;

    // 0) conversions + transpose
    {
        size_t nA = (size_t)Nn * P;
        cvt_split<<<(unsigned)((nA + 255) / 256), 256>>>(A, Ahi, Alo, nA);
        size_t nP = (size_t)Bb * P;
        cvt_split<<<(unsigned)((nP + 255) / 256), 256>>>(priv, Phi, Plo, nP);
        dim3 tg(P / 32, (Nn + 31) / 32);
        transpose_split<<<tg, dim3(32, 8)>>>(A, AThi, ATlo, Nn, P);
    }

    // 1) G = A A^T (mma bf16x3; 36 symmetric tiles x split-K 4 = 144 CTAs)
    {
        dim3 grid(36, 1, GSPLIT);
        mma_gemm<0, true><<<grid, 256, MM_SMEM>>>(Ahi, Alo, Ahi, Alo, Gpart,
                                                  Nn, Nn, P, P, Nn, 25000,
                                                  nullptr, nullptr);
        reduce_parts<<<(nG + 255) / 256, 256>>>(Gpart, G, nG, GSPLIT, nullptr);
    }

    // 2) c ~= 1.05*lambda_max(G); M = G/c
    pi_init<<<(Nn + 255) / 256, 256>>>(pv, Nn);
    for (int it = 0; it < 8; ++it) {
        pi_matvec<<<Nn, 128>>>(G, pv, pw, Nn);
        pi_normalize<<<1, 256>>>(pw, pv, Nn, cvals, (it == 7) ? 1 : 0);
    }
    scaleG_kernel<<<(nG + 255) / 256, 256>>>(G, cvals, nG);

    // 3) B = M^{-1}: 5 Newton-Schulz iterations (scalar, split-K=2)
    init_identity<<<(nG + 255) / 256, 256>>>(Bns, Nn);
    {
        float* Bc = Bns;
        float* Bo = B2ns;
        dim3 grid(8, 8, 2);
        for (int it = 0; it < NS_ITERS; ++it) {
            sgemm_nn<<<grid, 256>>>(G, Bc, Gpart, Nn, Nn, Nn, Nn, Nn, Nn, 504);
            reduce_parts<<<(nG + 255) / 256, 256>>>(Gpart, T, nG, 2, nullptr);
            sgemm_nn<<<grid, 256>>>(Bc, T, Gpart, Nn, Nn, Nn, Nn, Nn, Nn, 504);
            reduce_ns<<<(nG + 255) / 256, 256>>>(Gpart, Bc, Bo, nG, 2);
            float* tmp = Bc; Bc = Bo; Bo = tmp;
        }
        Bns = Bc;
    }

    // 4) Y = priv A^T (mma bf16x3; 16 tiles x split-K 9 = 144 CTAs)
    {
        dim3 grid(8, 2, YSPLIT);
        mma_gemm<0, false><<<grid, 256, MM_SMEM>>>(Phi, Plo, Ahi, Alo, Ypart,
                                                   Bb, Nn, P, P, Nn, 11112,
                                                   nullptr, nullptr);
        reduce_parts<<<(Bb * Nn + 255) / 256, 256>>>(Ypart, Yb, Bb * Nn, YSPLIT, nullptr);
    }

    // 5) X = Y * B * (1/c) (scalar, split-K=8)
    {
        dim3 grid(8, 2, 8);
        sgemm_nn<<<grid, 256>>>(Yb, Bns, Ypart, Bb, Nn, Nn, Nn, Nn, Nn, 128);
        reduce_parts<<<(Bb * Nn + 255) / 256, 256>>>(Ypart, X, Bb * Nn, 8, cvals + 1);
    }

    // 6) scale_b = min(1/||emb_b||, 1)
    calc_scale_kernel<<<Bb, 256>>>(Yb, X, scale, Nn);

    // 7) convert X, then out = scale[r]*(X A) + clamp(priv - X A, +-1e-3)
    {
        size_t nX = (size_t)Bb * Nn;
        cvt_split<<<(unsigned)((nX + 255) / 256), 256>>>(X, Xhi, Xlo, nX);
        dim3 grid((P + 127) / 128, (Bb + 127) / 128, 1);   // (782, 2)
        mma_gemm<2, false><<<grid, 256, MM_SMEM>>>(Xhi, Xlo, AThi, ATlo, out,
                                                   Bb, P, Nn, Nn, P, Nn,
                                                   scale, priv);
    }
    (void)in_sizes; (void)n_in; (void)out_size;
}